// round 16
// baseline (speedup 1.0000x reference)
#include <cuda_runtime.h>
#include <cuda_fp16.h>
#include <cstdint>

#define BB 4
#define SS 2048
#define EE 1024
#define DD 64

__device__ __align__(16) __half g_q [BB * SS * DD];   // scaled 1/8
__device__ __align__(16) __half g_k [BB * SS * DD];
__device__ __align__(16) __half g_vt[BB * DD * SS];   // [b][d][s]
__device__ __align__(16) __half g_Wt[192 * EE];
__device__ float g_part[BB * 32 * 8 * 64 * 64];
__device__ float g_ml  [BB * 32 * 8 * 128];

__device__ __forceinline__ uint32_t packh2(float a, float b) {
    __half2 h = __floats2half2_rn(a, b); return *(uint32_t*)&h;
}
__device__ __forceinline__ void mma_f16(float c[4], const uint32_t a[4],
                                        uint32_t b0, uint32_t b1) {
    asm volatile("mma.sync.aligned.m16n8k16.row.col.f32.f16.f16.f32 "
        "{%0,%1,%2,%3},{%4,%5,%6,%7},{%8,%9},{%0,%1,%2,%3};"
        : "+f"(c[0]), "+f"(c[1]), "+f"(c[2]), "+f"(c[3])
        : "r"(a[0]), "r"(a[1]), "r"(a[2]), "r"(a[3]), "r"(b0), "r"(b1));
}
__device__ __forceinline__ void cp16(uint32_t d, const void* s) {
    asm volatile("cp.async.cg.shared.global [%0], [%1], 16;" :: "r"(d), "l"(s));
}

// ---------------- W transpose + fp16 convert ----------------
__global__ __launch_bounds__(256) void wcvt(const float* __restrict__ Wq,
                                            const float* __restrict__ Wk,
                                            const float* __restrict__ Wv)
{
    __shared__ float Wt[64][65];
    const float* W = (blockIdx.y == 0) ? Wk : (blockIdx.y == 1 ? Wq : Wv);
    const int tid = threadIdx.x, k0 = blockIdx.x * 64;
    #pragma unroll
    for (int i = 0; i < 4; i++) {
        int idx = tid + 256 * i;
        int rr = idx >> 4, c4 = (idx & 15) * 4;
        float4 v = *(const float4*)&W[(size_t)(k0 + rr) * DD + c4];
        Wt[rr][c4] = v.x; Wt[rr][c4 + 1] = v.y;
        Wt[rr][c4 + 2] = v.z; Wt[rr][c4 + 3] = v.w;
    }
    __syncthreads();
    int n = tid >> 2, kk = (tid & 3) * 16;
    uint32_t u[8];
    #pragma unroll
    for (int j = 0; j < 8; j++)
        u[j] = packh2(Wt[kk + 2 * j][n], Wt[kk + 2 * j + 1][n]);
    __half* dst = &g_Wt[(size_t)(blockIdx.y * 64 + n) * EE + k0 + kk];
    *(uint4*)dst = *(uint4*)u;
    *(uint4*)(dst + 8) = *(uint4*)(u + 4);
}

// ---------------- fused QKV projection, fp16 mma ----------------
__global__ __launch_bounds__(256) void proj_f16(
    const float* __restrict__ x,
    const float* __restrict__ bq, const float* __restrict__ bk,
    const float* __restrict__ bv)
{
    __shared__ __align__(16) __half Xs[64 * 72];
    __shared__ __align__(16) __half Ws[192 * 72];
    const int tid = threadIdx.x, lane = tid & 31, wid = tid >> 5;
    const int wg = wid & 3, half = wid >> 2;
    const int r = lane >> 2, q = lane & 3;
    const int m0 = blockIdx.x * 64;

    float acc[12][4];
    #pragma unroll
    for (int i = 0; i < 12; i++)
        #pragma unroll
        for (int j = 0; j < 4; j++) acc[i][j] = 0.f;

    for (int k0 = 0; k0 < EE; k0 += 64) {
        #pragma unroll
        for (int i = 0; i < 6; i++) {
            int ch = tid + 256 * i;
            int rw = ch >> 3, c8 = (ch & 7) * 8;
            cp16((uint32_t)__cvta_generic_to_shared(&Ws[rw * 72 + c8]),
                 g_Wt + (size_t)rw * EE + k0 + c8);
        }
        asm volatile("cp.async.commit_group;");
        {
            int row = tid >> 2, c16 = (tid & 3) * 16;
            const float* xp = &x[(size_t)(m0 + row) * EE + k0 + c16];
            float4 v0 = *(const float4*)xp,       v1 = *(const float4*)(xp + 4);
            float4 v2 = *(const float4*)(xp + 8), v3 = *(const float4*)(xp + 12);
            uint4 u0 = make_uint4(packh2(v0.x, v0.y), packh2(v0.z, v0.w),
                                  packh2(v1.x, v1.y), packh2(v1.z, v1.w));
            uint4 u1 = make_uint4(packh2(v2.x, v2.y), packh2(v2.z, v2.w),
                                  packh2(v3.x, v3.y), packh2(v3.z, v3.w));
            *(uint4*)&Xs[row * 72 + c16] = u0;
            *(uint4*)&Xs[row * 72 + c16 + 8] = u1;
        }
        asm volatile("cp.async.wait_group 0;");
        __syncthreads();

        const uint32_t* Xu = (const uint32_t*)Xs;
        const uint32_t* Wu = (const uint32_t*)Ws;
        #pragma unroll
        for (int ks = 0; ks < 4; ks++) {
            uint32_t a[4];
            int ra = 16 * wg + r;
            a[0] = Xu[ra * 36 + 8 * ks + q];
            a[1] = Xu[(ra + 8) * 36 + 8 * ks + q];
            a[2] = Xu[ra * 36 + 8 * ks + 4 + q];
            a[3] = Xu[(ra + 8) * 36 + 8 * ks + 4 + q];
            #pragma unroll
            for (int nt = 0; nt < 12; nt++) {
                int n0 = (12 * half + nt) * 8 + r;
                mma_f16(acc[nt], a, Wu[n0 * 36 + 8 * ks + q],
                        Wu[n0 * 36 + 8 * ks + 4 + q]);
            }
        }
        __syncthreads();
    }

    #pragma unroll
    for (int nt = 0; nt < 12; nt++) {
        int ng = (12 * half + nt) * 8 + 2 * q;
        int blk = ng >> 6, nn = ng & 63;
        const float* bias = (blk == 0) ? bk : (blk == 1 ? bq : bv);
        float b0v = bias[nn], b1v = bias[nn + 1];
        int m = m0 + 16 * wg + r;
        float v00 = acc[nt][0] + b0v, v01 = acc[nt][1] + b1v;
        float v10 = acc[nt][2] + b0v, v11 = acc[nt][3] + b1v;
        if (blk == 0) {
            *(uint32_t*)&g_q[(size_t)m * DD + nn] = packh2(v00 * .125f, v01 * .125f);
            *(uint32_t*)&g_q[(size_t)(m + 8) * DD + nn] = packh2(v10 * .125f, v11 * .125f);
        } else if (blk == 1) {
            *(uint32_t*)&g_k[(size_t)m * DD + nn]       = packh2(v00, v01);
            *(uint32_t*)&g_k[(size_t)(m + 8) * DD + nn] = packh2(v10, v11);
        } else {
            int bb = m >> 11, s = m & (SS - 1);
            size_t base = ((size_t)bb * DD + nn) * SS + s;
            g_vt[base]          = __float2half(v00);
            g_vt[base + SS]     = __float2half(v01);
            g_vt[base + 8]      = __float2half(v10);
            g_vt[base + SS + 8] = __float2half(v11);
        }
    }
}

// ---------------- flash phase A: chunk of <=4 KV tiles ----------------
#define KH 72
#define OSTR 68
#define SM_PART (4 * 64 * KH * 2 * 2 + 1024)   // 74752 B
__global__ __launch_bounds__(256) void flash_part(float* __restrict__ out)
{
    extern __shared__ __align__(16) char smraw[];
    __half* Kt = (__half*)smraw;
    __half* Vt = Kt + 4 * 64 * KH;
    float* mlb = (float*)(smraw + 4 * 64 * KH * 2 * 2);
    float* Of  = (float*)smraw;

    const int ck = blockIdx.x, qt = blockIdx.y, b = blockIdx.z;
    const int T = qt + 1, t0 = ck * 4;
    if (t0 >= T) return;
    const int nloc = min(4, T - t0), nc = (T + 3) >> 2;

    const int tid = threadIdx.x, lane = tid & 31, wid = tid >> 5;
    const int wg = wid & 3, g = wid >> 2;
    const int r = lane >> 2, q = lane & 3;
    const int q0 = qt * 64, rA = 16 * wg + r;

    const __half* gq = g_q + (size_t)(b * SS + q0 + 16 * wg) * DD;
    const __half* gk = g_k + (size_t)b * SS * DD;
    const __half* gv = g_vt + (size_t)b * DD * SS;

    #pragma unroll
    for (int pr = 0; pr < 2; pr++) {
        #pragma unroll
        for (int t2 = 0; t2 < 2; t2++) {
            int tl = pr * 2 + t2;
            if (tl < nloc) {
                int k0c = (t0 + tl) * 64;
                #pragma unroll
                for (int i = 0; i < 2; i++) {
                    int idx = tid + i * 256;
                    int row = idx >> 3, c8 = (idx & 7) * 8;
                    cp16((uint32_t)__cvta_generic_to_shared(
                             &Kt[(tl * 64 + row) * KH + c8]),
                         gk + (size_t)(k0c + row) * DD + c8);
                    cp16((uint32_t)__cvta_generic_to_shared(
                             &Vt[(tl * 64 + row) * KH + c8]),
                         gv + (size_t)row * SS + k0c + c8);
                }
            }
        }
        asm volatile("cp.async.commit_group;");
    }

    uint32_t qa[4][4];
    #pragma unroll
    for (int ks = 0; ks < 4; ks++) {
        int c0 = 16 * ks + 2 * q;
        qa[ks][0] = *(const uint32_t*)&gq[(size_t)r * DD + c0];
        qa[ks][1] = *(const uint32_t*)&gq[(size_t)(r + 8) * DD + c0];
        qa[ks][2] = *(const uint32_t*)&gq[(size_t)r * DD + c0 + 8];
        qa[ks][3] = *(const uint32_t*)&gq[(size_t)(r + 8) * DD + c0 + 8];
    }

    float o[8][4];
    #pragma unroll
    for (int i = 0; i < 8; i++)
        #pragma unroll
        for (int j = 0; j < 4; j++) o[i][j] = 0.f;
    float m0r = -1e30f, m1r = -1e30f, l0r = 0.f, l1r = 0.f;

    #pragma unroll
    for (int si = 0; si < 2; si++) {
        if (2 * si >= nloc) break;
        if (si == 0) asm volatile("cp.async.wait_group 1;");
        else         asm volatile("cp.async.wait_group 0;");
        __syncthreads();

        int tl = 2 * si + g;
        if (tl < nloc) {
            int gt = t0 + tl;
            const __half* KD = Kt + tl * 64 * KH;
            const __half* VD = Vt + tl * 64 * KH;

            float s[8][4];
            #pragma unroll
            for (int i = 0; i < 8; i++)
                #pragma unroll
                for (int j = 0; j < 4; j++) s[i][j] = 0.f;
            #pragma unroll
            for (int ks = 0; ks < 4; ks++)
                #pragma unroll
                for (int nt = 0; nt < 8; nt++) {
                    uint32_t b0 = *(const uint32_t*)&KD[(8 * nt + r) * KH + 16 * ks + 2 * q];
                    uint32_t b1 = *(const uint32_t*)&KD[(8 * nt + r) * KH + 16 * ks + 8 + 2 * q];
                    mma_f16(s[nt], qa[ks], b0, b1);
                }

            if (gt == qt) {
                int rB = rA + 8;
                #pragma unroll
                for (int nt = 0; nt < 8; nt++) {
                    int c0 = 8 * nt + 2 * q;
                    if (c0     > rA) s[nt][0] = -1e30f;
                    if (c0 + 1 > rA) s[nt][1] = -1e30f;
                    if (c0     > rB) s[nt][2] = -1e30f;
                    if (c0 + 1 > rB) s[nt][3] = -1e30f;
                }
            }

            float pm0 = -1e30f, pm1 = -1e30f;
            #pragma unroll
            for (int nt = 0; nt < 8; nt++) {
                pm0 = fmaxf(pm0, fmaxf(s[nt][0], s[nt][1]));
                pm1 = fmaxf(pm1, fmaxf(s[nt][2], s[nt][3]));
            }
            pm0 = fmaxf(pm0, __shfl_xor_sync(~0u, pm0, 1));
            pm0 = fmaxf(pm0, __shfl_xor_sync(~0u, pm0, 2));
            pm1 = fmaxf(pm1, __shfl_xor_sync(~0u, pm1, 1));
            pm1 = fmaxf(pm1, __shfl_xor_sync(~0u, pm1, 2));
            float mn0 = fmaxf(m0r, pm0), mn1 = fmaxf(m1r, pm1);
            float c0f = __expf(m0r - mn0), c1f = __expf(m1r - mn1);
            m0r = mn0; m1r = mn1;
            float su0 = 0.f, su1 = 0.f;
            #pragma unroll
            for (int nt = 0; nt < 8; nt++) {
                s[nt][0] = __expf(s[nt][0] - m0r);
                s[nt][1] = __expf(s[nt][1] - m0r);
                s[nt][2] = __expf(s[nt][2] - m1r);
                s[nt][3] = __expf(s[nt][3] - m1r);
                su0 += s[nt][0] + s[nt][1];
                su1 += s[nt][2] + s[nt][3];
            }
            su0 += __shfl_xor_sync(~0u, su0, 1);
            su0 += __shfl_xor_sync(~0u, su0, 2);
            su1 += __shfl_xor_sync(~0u, su1, 1);
            su1 += __shfl_xor_sync(~0u, su1, 2);
            l0r = l0r * c0f + su0;  l1r = l1r * c1f + su1;
            #pragma unroll
            for (int nt = 0; nt < 8; nt++) {
                o[nt][0] *= c0f; o[nt][1] *= c0f;
                o[nt][2] *= c1f; o[nt][3] *= c1f;
            }
            #pragma unroll
            for (int t = 0; t < 4; t++) {
                uint32_t pa[4];
                pa[0] = packh2(s[2 * t][0],     s[2 * t][1]);
                pa[1] = packh2(s[2 * t][2],     s[2 * t][3]);
                pa[2] = packh2(s[2 * t + 1][0], s[2 * t + 1][1]);
                pa[3] = packh2(s[2 * t + 1][2], s[2 * t + 1][3]);
                #pragma unroll
                for (int nt = 0; nt < 8; nt++) {
                    uint32_t b0 = *(const uint32_t*)&VD[(8 * nt + r) * KH + 16 * t + 2 * q];
                    uint32_t b1 = *(const uint32_t*)&VD[(8 * nt + r) * KH + 16 * t + 8 + 2 * q];
                    mma_f16(o[nt], pa, b0, b1);
                }
            }
        }
    }

    // merge groups
    __syncthreads();
    if (q == 0) {
        mlb[g * 64 + rA]           = m0r;
        mlb[g * 64 + rA + 8]       = m1r;
        mlb[128 + g * 64 + rA]     = l0r;
        mlb[128 + g * 64 + rA + 8] = l1r;
    }
    __syncthreads();
    int og = 1 - g;
    float mo0 = mlb[og * 64 + rA],       mo1 = mlb[og * 64 + rA + 8];
    float lo0 = mlb[128 + og * 64 + rA], lo1 = mlb[128 + og * 64 + rA + 8];
    float M0 = fmaxf(m0r, mo0), M1 = fmaxf(m1r, mo1);
    float sc0 = __expf(m0r - M0), sc1 = __expf(m1r - M1);
    float L0 = l0r * sc0 + lo0 * __expf(mo0 - M0);
    float L1 = l1r * sc1 + lo1 * __expf(mo1 - M1);
    __syncthreads();
    if (g == 1) {
        #pragma unroll
        for (int nt = 0; nt < 8; nt++) {
            int cc = 8 * nt + 2 * q;
            *(float2*)&Of[rA * OSTR + cc] =
                make_float2(o[nt][0] * sc0, o[nt][1] * sc0);
            *(float2*)&Of[(rA + 8) * OSTR + cc] =
                make_float2(o[nt][2] * sc1, o[nt][3] * sc1);
        }
    }
    __syncthreads();
    if (g == 0) {
        if (nc == 1) {
            float* ob = out + (size_t)(b * SS + q0) * DD;
            float i0 = 1.f / L0, i1 = 1.f / L1;
            #pragma unroll
            for (int nt = 0; nt < 8; nt++) {
                int cc = 8 * nt + 2 * q;
                float2 s0 = *(float2*)&Of[rA * OSTR + cc];
                float2 s1 = *(float2*)&Of[(rA + 8) * OSTR + cc];
                *(float2*)&ob[(size_t)rA * DD + cc] = make_float2(
                    (o[nt][0] * sc0 + s0.x) * i0, (o[nt][1] * sc0 + s0.y) * i0);
                *(float2*)&ob[(size_t)(rA + 8) * DD + cc] = make_float2(
                    (o[nt][2] * sc1 + s1.x) * i1, (o[nt][3] * sc1 + s1.y) * i1);
            }
        } else {
            size_t pb = (size_t)(b * 32 + qt) * 8 + ck;
            float* op = &g_part[pb * 4096];
            #pragma unroll
            for (int nt = 0; nt < 8; nt++) {
                int cc = 8 * nt + 2 * q;
                float2 s0 = *(float2*)&Of[rA * OSTR + cc];
                float2 s1 = *(float2*)&Of[(rA + 8) * OSTR + cc];
                *(float2*)&op[rA * 64 + cc] =
                    make_float2(o[nt][0] * sc0 + s0.x, o[nt][1] * sc0 + s0.y);
                *(float2*)&op[(rA + 8) * 64 + cc] =
                    make_float2(o[nt][2] * sc1 + s1.x, o[nt][3] * sc1 + s1.y);
            }
            if (q == 0) {
                float* mp = &g_ml[pb * 128];
                mp[rA] = M0;  mp[rA + 8] = M1;
                mp[64 + rA] = L0;  mp[64 + rA + 8] = L1;
            }
        }
    }
}

// ---------------- flash phase B: one warp per row, fully unrolled MLP ------
__global__ __launch_bounds__(256) void flash_merge(float* __restrict__ out)
{
    const int gr = blockIdx.x * 8 + (threadIdx.x >> 5);
    const int lane = threadIdx.x & 31;
    const int b = gr >> 11, s = gr & (SS - 1), qt = s >> 6;
    const int nc = (qt + 4) >> 2;
    if (nc < 2) return;   // written directly by flash_part
    const int row = s & 63;
    const size_t pb = (size_t)(b * 32 + qt) * 8;

    // issue ALL loads before any math (MLP ~ 16)
    float mv[8], lv[8];
    #pragma unroll
    for (int c = 0; c < 8; c++) {
        if (c < nc) {
            mv[c] = g_ml[(pb + c) * 128 + row];
            lv[c] = g_ml[(pb + c) * 128 + 64 + row];
        } else { mv[c] = -1e30f; lv[c] = 0.f; }
    }
    float2 pv[8];
    #pragma unroll
    for (int c = 0; c < 8; c++)
        pv[c] = (c < nc)
            ? *(const float2*)&g_part[(pb + c) * 4096 + row * 64 + lane * 2]
            : make_float2(0.f, 0.f);

    float M = mv[0];
    #pragma unroll
    for (int c = 1; c < 8; c++) M = fmaxf(M, mv[c]);
    float L = 0.f;
    float2 acc = make_float2(0.f, 0.f);
    #pragma unroll
    for (int c = 0; c < 8; c++) {
        float w = __expf(mv[c] - M);   // padding lanes: exp(-huge) == 0
        L += lv[c] * w;
        acc.x += w * pv[c].x;  acc.y += w * pv[c].y;
    }
    float inv = 1.f / L;
    *(float2*)&out[(size_t)gr * DD + lane * 2] =
        make_float2(acc.x * inv, acc.y * inv);
}

extern "C" void kernel_launch(void* const* d_in, const int* in_sizes, int n_in,
                              void* d_out, int out_size)
{
    const float* x  = (const float*)d_in[0];
    const float* Wq = (const float*)d_in[2];
    const float* bq = (const float*)d_in[3];
    const float* Wk = (const float*)d_in[4];
    const float* bk = (const float*)d_in[5];
    const float* Wv = (const float*)d_in[6];
    const float* bv = (const float*)d_in[7];
    float* out = (float*)d_out;

    cudaFuncSetAttribute(flash_part,
                         cudaFuncAttributeMaxDynamicSharedMemorySize, SM_PART);
    wcvt<<<dim3(16, 3), 256>>>(Wq, Wk, Wv);
    proj_f16<<<BB * SS / 64, 256>>>(x, bq, bk, bv);
    flash_part<<<dim3(8, 32, BB), 256, SM_PART>>>(out);
    flash_merge<<<BB * SS / 8, 256>>>(out);
}